// round 1
// baseline (speedup 1.0000x reference)
#include <cuda_runtime.h>

// RateBasedNeuron: N=2^23 step neuron sim.
//  rate[t] = (1-alpha)*rate[t-1] + alpha*I[t], rate[0]=0, alpha = 1/tau
//  p[t] = clip(rate[t]/threshold, 0, 1) * 0.1
//  refractory DFA over states {0,1,2}; spike[t] = 1.0 if fired.
//
// Parallelization: the IIR is contractive (a=0.95) -> per-block halo of 1024
// steps from rate=0 reproduces true rate to ~1e-10. The 3-state DFA collapses
// to state 0 after any two consecutive non-fire steps -> 64-step per-thread
// warm-up reconstructs exact state. => fully independent blocks, one launch.

#define THREADS 512
#define ITEMS   18
#define REGION  (THREADS * ITEMS)   // 9216 elements per block
#define HALO    1024
#define TILE    (REGION - HALO)     // 8192 output elements per block
#define WARMUP  64

__global__ void __launch_bounds__(THREADS, 2)
neuron_kernel(const float* __restrict__ gI, const float* __restrict__ gU,
              const float* __restrict__ gTau, const float* __restrict__ gThr,
              float* __restrict__ gOut, int N)
{
    extern __shared__ float smem[];
    float* sP = smem;                // [REGION] b -> p -> spikes (reused)
    float* sU = smem + REGION;       // [REGION] uniforms
    float* sA = smem + 2 * REGION;   // [THREADS] scan A
    float* sS = sA + THREADS;        // [THREADS] scan B

    const int tid = threadIdx.x;
    const float tau = gTau[0];
    const float thr = gThr[0];
    const float alpha = __fdiv_rn(1.0f, tau);   // DT=1
    const float a = 1.0f - alpha;

    const long long base = (long long)blockIdx.x * TILE - HALO;

    // ---- Stage coalesced loads into shared ----
    for (int k = tid; k < REGION; k += THREADS) {
        long long g = base + k;
        float b = 0.0f;   // g==0 -> rate[0]=0 means b_0=0; g<0 halo -> 0
        float uu = 1.0f;  // g<0 halo: u=1 >= p always -> never fires
        if (g >= 1 && g < (long long)N) b = alpha * gI[g];
        if (g >= 0 && g < (long long)N) uu = gU[g];
        sP[k] = b;
        sU[k] = uu;
    }
    __syncthreads();

    // ---- Pass 1: thread-local affine reduce (r_out = A*r_in + B, r_in=0) ----
    const int s0 = tid * ITEMS;
    float B = 0.0f;
    float A = 1.0f;
    #pragma unroll
    for (int k = 0; k < ITEMS; k++) {
        B = fmaf(a, B, sP[s0 + k]);
        A *= a;
    }
    sA[tid] = A;
    sS[tid] = B;
    __syncthreads();

    // ---- Kogge-Stone inclusive scan of affine maps across threads ----
    float Acur = A, Bcur = B;
    for (int d = 1; d < THREADS; d <<= 1) {
        float Al = 1.0f, Bl = 0.0f;
        if (tid >= d) { Al = sA[tid - d]; Bl = sS[tid - d]; }
        __syncthreads();
        if (tid >= d) {
            Bcur = fmaf(Bl, Acur, Bcur);   // compose: left then right
            Acur *= Al;                    // (underflows to 0 at large spans: fine)
            sA[tid] = Acur;
            sS[tid] = Bcur;
        }
        __syncthreads();
    }
    const float rin = (tid == 0) ? 0.0f : sS[tid - 1];  // exclusive, zero init

    // ---- Pass 2: finalize rate, write firing_prob p in place of b ----
    float r = rin;
    #pragma unroll
    for (int k = 0; k < ITEMS; k++) {
        r = fmaf(a, r, sP[s0 + k]);
        float q = __fdiv_rn(r, thr);                 // match reference: fp32 div.rn
        q = fminf(fmaxf(q, 0.0f), 1.0f) * 0.1f;      // clip * (DT/10)
        sP[s0 + k] = q;
    }
    __syncthreads();

    // ---- DFA: 64-step warm-up from state 0, then emit 18 spikes ----
    int kstart = s0 - WARMUP;
    if (kstart < 0) kstart = 0;
    int refrac = 0;
    for (int k = kstart; k < s0; k++) {
        float pt = sP[k];
        float ut = sU[k];
        bool fire = (refrac == 0) && (ut < pt);
        refrac = fire ? 2 : (refrac > 0 ? refrac - 1 : 0);
    }
    unsigned int spk = 0;
    #pragma unroll
    for (int k = 0; k < ITEMS; k++) {
        float pt = sP[s0 + k];
        float ut = sU[s0 + k];
        bool fire = (refrac == 0) && (ut < pt);
        if (fire) spk |= (1u << k);
        refrac = fire ? 2 : (refrac > 0 ? refrac - 1 : 0);
    }
    __syncthreads();

    // ---- Scatter spikes to shared, coalesced store of tile ----
    #pragma unroll
    for (int k = 0; k < ITEMS; k++)
        sP[s0 + k] = ((spk >> k) & 1u) ? 1.0f : 0.0f;
    __syncthreads();

    const long long obase = (long long)blockIdx.x * TILE;
    for (int k = tid; k < TILE; k += THREADS) {
        long long g = obase + k;
        if (g < (long long)N) gOut[g] = sP[HALO + k];
    }
}

extern "C" void kernel_launch(void* const* d_in, const int* in_sizes, int n_in,
                              void* d_out, int out_size)
{
    const float* I   = (const float*)d_in[0];
    const float* u   = (const float*)d_in[1];
    const float* tau = (const float*)d_in[2];
    const float* thr = (const float*)d_in[3];
    float* out = (float*)d_out;
    const int N = in_sizes[0];

    const int blocks = (N + TILE - 1) / TILE;
    const size_t smem = (size_t)(2 * REGION + 2 * THREADS) * sizeof(float);

    // Idempotent; not a stream op, safe under graph capture.
    cudaFuncSetAttribute(neuron_kernel,
                         cudaFuncAttributeMaxDynamicSharedMemorySize, (int)smem);

    neuron_kernel<<<blocks, THREADS, smem>>>(I, u, tau, thr, out, N);
}

// round 2
// speedup vs baseline: 1.5614x; 1.5614x over previous
#include <cuda_runtime.h>

// RateBasedNeuron: N=2^23 neuron sim, fully parallel formulation.
//  rate[t] = a*rate[t-1] + alpha*I[t]  (a = 1-1/tau, contractive)
//  p[t] = clip(rate/thr,0,1)*0.1 ; 3-state refractory DFA -> spikes.
//
// Per-block 512-step halo (a^512*50 ~ 2e-10) makes blocks independent for the
// IIR; the same halo warms up the refractory DFA (collapses to state 0 after
// any 2 consecutive non-fires). Within a block:
//   - affine IIR scan via warp shuffles + 8 warp aggregates
//   - refractory DFA as exact function composition: 3-byte state map,
//     composed with one __byte_perm per scan step; per-thread spike bits
//     via find-lowest-set loop over eligibility mask (avg <1 iteration).

#define THREADS 256
#define ITEMS   16
#define REGION  (THREADS * ITEMS)    // 4096
#define HALO    512
#define TILE    (REGION - HALO)      // 3584
#define PREG    (REGION + REGION/16) // 4352 padded floats (stride 17)
#define FULLMASK 0xffffffffu
#define IDMAP   0x00020100u          // identity state map: bytes [0,1,2]

__device__ __forceinline__ int pad(int i) { return i + (i >> 4); }

__global__ void __launch_bounds__(THREADS, 6)
neuron_kernel(const float* __restrict__ gI, const float* __restrict__ gU,
              const float* __restrict__ gTau, const float* __restrict__ gThr,
              float* __restrict__ gOut, int N)
{
    extern __shared__ float smem[];
    float* sP = smem;                 // [PREG] b-values, later spikes
    float* sU = smem + PREG;          // [PREG] uniforms
    float* wA = sU + PREG;            // [8] warp affine A
    float* wB = wA + 8;               // [8] warp affine B
    unsigned* wS = (unsigned*)(wB + 8); // [8] warp DFA maps

    const int tid  = threadIdx.x;
    const int lane = tid & 31;
    const int wid  = tid >> 5;

    const float tau = gTau[0];
    const float thr = gThr[0];
    const float alpha = __fdiv_rn(1.0f, tau);
    const float a = 1.0f - alpha;

    const long long base = (long long)blockIdx.x * TILE - HALO;

    // ---- Stage coalesced loads into padded shared ----
    for (int k = tid; k < REGION; k += THREADS) {
        long long g = base + k;
        float b  = 0.0f;   // g==0: rate[0]=0 => b=0 ; g<0 halo: 0
        float uu = 1.0f;   // halo u=1 => never fires
        if (g >= 1 && g < (long long)N) b  = alpha * gI[g];
        if (g >= 0 && g < (long long)N) uu = gU[g];
        int pk = pad(k);
        sP[pk] = b;
        sU[pk] = uu;
    }
    __syncthreads();

    // ---- Pass 1: thread-local affine reduce (r -> A*r + B) ----
    const int pbase = 17 * tid;       // pad(16*tid)
    float B = 0.0f;
    #pragma unroll
    for (int j = 0; j < ITEMS; j++)
        B = fmaf(a, B, sP[pbase + j]);
    float a2 = a * a, a4 = a2 * a2, a8 = a4 * a4;
    float A = a8 * a8;                // a^16

    // ---- Intra-warp inclusive shuffle scan of affine maps ----
    float Ai = A, Bi = B;
    #pragma unroll
    for (int d = 1; d < 32; d <<= 1) {
        float Au = __shfl_up_sync(FULLMASK, Ai, d);
        float Bu = __shfl_up_sync(FULLMASK, Bi, d);
        if (lane >= d) { Bi = fmaf(Bu, Ai, Bi); Ai *= Au; }
    }
    if (lane == 31) { wA[wid] = Ai; wB[wid] = Bi; }
    __syncthreads();

    // Warp-prefix affine (compose aggregates of warps < wid; r0 = 0)
    float Bp = 0.0f;
    #pragma unroll
    for (int w = 0; w < 7; w++)
        if (w < wid) Bp = fmaf(wA[w], Bp, wB[w]);
    // Exclusive prefix for this thread
    float Aprev = __shfl_up_sync(FULLMASK, Ai, 1);
    float Bprev = __shfl_up_sync(FULLMASK, Bi, 1);
    float rin = (lane == 0) ? Bp : fmaf(Aprev, Bp, Bprev);

    // ---- Pass 2: finalize rates, build eligibility bits (p stays in regs) --
    float r = rin;
    unsigned e = 0;
    #pragma unroll
    for (int j = 0; j < ITEMS; j++) {
        r = fmaf(a, r, sP[pbase + j]);
        float q = __fdiv_rn(r, thr);                 // match reference div.rn
        q = fminf(fmaxf(q, 0.0f), 1.0f) * 0.1f;
        float ut = sU[pbase + j];
        e |= (ut < q ? 1u : 0u) << j;
    }

    // ---- DFA: spikes + outgoing state for each incoming state s in {0,1,2} -
    unsigned spk0, spk1, spk2, fmap;
    {
        unsigned sp[3];
        unsigned out[3];
        #pragma unroll
        for (int s = 0; s < 3; s++) {
            unsigned es = e & ~((1u << s) - 1u);
            unsigned sk = 0;
            while (es) {
                unsigned b = es & (0u - es);         // lowest eligible fire
                sk |= b;
                es &= ~(b | (b << 1) | (b << 2));    // refractory suppression
            }
            sp[s] = sk;
            int hb = sk ? (31 - __clz(sk)) : -100;   // highest fire position
            int o = hb + 3 - ITEMS;                  // leftover refractory
            out[s] = (o > 0) ? (unsigned)o : 0u;
        }
        spk0 = sp[0]; spk1 = sp[1]; spk2 = sp[2];
        fmap = out[0] | (out[1] << 8) | (out[2] << 16);
    }

    // ---- Intra-warp scan of state maps (compose = one __byte_perm) ----
    unsigned Fi = fmap;
    #pragma unroll
    for (int d = 1; d < 32; d <<= 1) {
        unsigned Fu = __shfl_up_sync(FULLMASK, Fi, d);
        if (lane >= d) Fi = __byte_perm(Fi, 0, Fu);  // Fi o Fu
    }
    if (lane == 31) wS[wid] = Fi;
    __syncthreads();

    unsigned Sp = IDMAP;
    #pragma unroll
    for (int w = 0; w < 7; w++)
        if (w < wid) Sp = __byte_perm(wS[w], 0, Sp);
    unsigned Fprev = __shfl_up_sync(FULLMASK, Fi, 1);
    unsigned X = (lane == 0) ? Sp : __byte_perm(Fprev, 0, Sp);
    unsigned s_in = X & 3u;                          // state entering this thread

    unsigned spikes = (s_in == 0) ? spk0 : ((s_in == 1) ? spk1 : spk2);

    // ---- Scatter spike floats to shared, coalesced store ----
    #pragma unroll
    for (int j = 0; j < ITEMS; j++)
        sP[pbase + j] = ((spikes >> j) & 1u) ? 1.0f : 0.0f;
    __syncthreads();

    const long long obase = (long long)blockIdx.x * TILE;
    #pragma unroll
    for (int k = tid; k < TILE; k += THREADS) {      // 14 iters
        long long g = obase + k;
        if (g < (long long)N) gOut[g] = sP[pad(HALO + k)];
    }
}

extern "C" void kernel_launch(void* const* d_in, const int* in_sizes, int n_in,
                              void* d_out, int out_size)
{
    const float* I   = (const float*)d_in[0];
    const float* u   = (const float*)d_in[1];
    const float* tau = (const float*)d_in[2];
    const float* thr = (const float*)d_in[3];
    float* out = (float*)d_out;
    const int N = in_sizes[0];

    const int blocks = (N + TILE - 1) / TILE;        // 2341
    const size_t smem = (size_t)(2 * PREG + 16 + 8) * sizeof(float);

    neuron_kernel<<<blocks, THREADS, smem>>>(I, u, tau, thr, out, N);
}

// round 3
// speedup vs baseline: 1.5648x; 1.0021x over previous
#include <cuda_runtime.h>

// RateBasedNeuron: N=2^23 neuron sim, fully parallel formulation.
//  rate[t] = a*rate[t-1] + alpha*I[t]  (a = 1-1/tau, contractive)
//  p[t] = clip(rate/thr,0,1)*0.1 ; 3-state refractory DFA -> spikes.
//
// Per-block 512-step halo (a^512*50 ~ 2e-10) makes blocks independent for the
// IIR; the same halo warms up the refractory DFA. v3: full float4 data path,
// ITEMS=32/thread, conflict-free padding (+4 words / 32 elems), interior
// fast path without predicates.

#define THREADS 256
#define ITEMS   32
#define REGION  (THREADS * ITEMS)        // 8192
#define HALO    512
#define TILE    (REGION - HALO)          // 7680
#define AWORDS  (REGION + (REGION >> 5) * 4)  // 9216 words per array
#define FULLMASK 0xffffffffu
#define IDMAP   0x00020100u              // identity state map bytes [0,1,2]

__device__ __forceinline__ int padw(int e)   { return e + ((e >> 5) << 2); }
__device__ __forceinline__ int padw4(int k4) { return 4 * k4 + ((k4 >> 3) << 2); }

__global__ void __launch_bounds__(THREADS, 3)
neuron_kernel(const float* __restrict__ gI, const float* __restrict__ gU,
              const float* __restrict__ gTau, const float* __restrict__ gThr,
              float* __restrict__ gOut, int N)
{
    extern __shared__ float smem[];
    float* sB = smem;                    // [AWORDS] alpha*I (padded)
    float* sU = smem + AWORDS;          // [AWORDS] uniforms, later spikes
    float* wA = sU + AWORDS;            // [8]
    float* wB = wA + 8;                 // [8]
    unsigned* wS = (unsigned*)(wB + 8); // [8]

    const int tid  = threadIdx.x;
    const int lane = tid & 31;
    const int wid  = tid >> 5;

    const float alpha = __fdiv_rn(1.0f, gTau[0]);
    const float thr   = gThr[0];
    const float a = 1.0f - alpha;

    const long long base = (long long)blockIdx.x * TILE - HALO;
    const bool interior = (base >= 1) && (base + REGION <= (long long)N);

    // ---- Stage (vectorized fast path; scalar guarded path for 2 edge blocks)
    if (interior) {
        const float4* gI4 = (const float4*)(gI + base);
        const float4* gU4 = (const float4*)(gU + base);
        #pragma unroll
        for (int it = 0; it < REGION / 4 / THREADS; it++) {   // 8 iters
            int k4 = tid + it * THREADS;
            float4 bi = gI4[k4];
            float4 uu = gU4[k4];
            bi.x *= alpha; bi.y *= alpha; bi.z *= alpha; bi.w *= alpha;
            int w = padw4(k4);
            *(float4*)(sB + w) = bi;
            *(float4*)(sU + w) = uu;
        }
    } else {
        for (int k = tid; k < REGION; k += THREADS) {
            long long g = base + k;
            float b = 0.0f, uu = 1.0f;   // halo g<0: b=0,u=1 ; g==0: b=0
            if (g >= 1 && g < (long long)N) b  = alpha * gI[g];
            if (g >= 0 && g < (long long)N) uu = gU[g];
            int w = padw(k);
            sB[w] = b; sU[w] = uu;
        }
    }
    __syncthreads();

    // ---- Pass 1: thread-local affine reduce (r -> A*r + B) ----
    const int tb = 36 * tid;             // padded word base, 16B aligned
    float B = 0.0f;
    #pragma unroll
    for (int c = 0; c < 8; c++) {
        float4 b4 = *(const float4*)(sB + tb + 4 * c);
        B = fmaf(a, B, b4.x); B = fmaf(a, B, b4.y);
        B = fmaf(a, B, b4.z); B = fmaf(a, B, b4.w);
    }
    float a2 = a * a, a4 = a2 * a2, a8 = a4 * a4, a16 = a8 * a8;
    float A = a16 * a16;                 // a^32

    // ---- Intra-warp inclusive shuffle scan of affine maps ----
    float Ai = A, Bi = B;
    #pragma unroll
    for (int d = 1; d < 32; d <<= 1) {
        float Au = __shfl_up_sync(FULLMASK, Ai, d);
        float Bu = __shfl_up_sync(FULLMASK, Bi, d);
        if (lane >= d) { Bi = fmaf(Bu, Ai, Bi); Ai *= Au; }
    }
    if (lane == 31) { wA[wid] = Ai; wB[wid] = Bi; }
    __syncthreads();

    // Warp-prefix affine (r0 = 0), then exclusive per-thread prefix
    float Bp = 0.0f;
    #pragma unroll
    for (int w = 0; w < 7; w++)
        if (w < wid) Bp = fmaf(wA[w], Bp, wB[w]);
    float Aprev = __shfl_up_sync(FULLMASK, Ai, 1);
    float Bprev = __shfl_up_sync(FULLMASK, Bi, 1);
    float rin = (lane == 0) ? Bp : fmaf(Aprev, Bp, Bprev);

    // ---- Pass 2: finalize rates, build eligibility bits ----
    float r = rin;
    unsigned e = 0;
    #pragma unroll
    for (int c = 0; c < 8; c++) {
        float4 b4 = *(const float4*)(sB + tb + 4 * c);
        float4 u4 = *(const float4*)(sU + tb + 4 * c);
        float q;
        r = fmaf(a, r, b4.x);
        q = __fdiv_rn(r, thr); q = fminf(fmaxf(q, 0.0f), 1.0f) * 0.1f;
        e |= (u4.x < q ? 1u : 0u) << (4 * c + 0);
        r = fmaf(a, r, b4.y);
        q = __fdiv_rn(r, thr); q = fminf(fmaxf(q, 0.0f), 1.0f) * 0.1f;
        e |= (u4.y < q ? 1u : 0u) << (4 * c + 1);
        r = fmaf(a, r, b4.z);
        q = __fdiv_rn(r, thr); q = fminf(fmaxf(q, 0.0f), 1.0f) * 0.1f;
        e |= (u4.z < q ? 1u : 0u) << (4 * c + 2);
        r = fmaf(a, r, b4.w);
        q = __fdiv_rn(r, thr); q = fminf(fmaxf(q, 0.0f), 1.0f) * 0.1f;
        e |= (u4.w < q ? 1u : 0u) << (4 * c + 3);
    }

    // ---- DFA: spikes + outgoing state for each incoming state s in {0,1,2} -
    unsigned spk0, spk1, spk2, fmap;
    {
        unsigned sp[3], out[3];
        #pragma unroll
        for (int s = 0; s < 3; s++) {
            unsigned es = e & ~((1u << s) - 1u);
            unsigned sk = 0;
            while (es) {
                unsigned b = es & (0u - es);           // lowest eligible fire
                sk |= b;
                es &= ~(b | (b << 1) | (b << 2));      // refractory suppression
            }
            sp[s] = sk;
            int hb = sk ? (31 - __clz(sk)) : -100;
            int o = hb + 3 - ITEMS;                    // leftover refractory
            out[s] = (o > 0) ? (unsigned)o : 0u;
        }
        spk0 = sp[0]; spk1 = sp[1]; spk2 = sp[2];
        fmap = out[0] | (out[1] << 8) | (out[2] << 16);
    }

    // ---- Intra-warp scan of state maps (compose = one __byte_perm) ----
    unsigned Fi = fmap;
    #pragma unroll
    for (int d = 1; d < 32; d <<= 1) {
        unsigned Fu = __shfl_up_sync(FULLMASK, Fi, d);
        if (lane >= d) Fi = __byte_perm(Fi, 0, Fu);
    }
    if (lane == 31) wS[wid] = Fi;
    __syncthreads();

    unsigned Sp = IDMAP;
    #pragma unroll
    for (int w = 0; w < 7; w++)
        if (w < wid) Sp = __byte_perm(wS[w], 0, Sp);
    unsigned Fprev = __shfl_up_sync(FULLMASK, Fi, 1);
    unsigned X = (lane == 0) ? Sp : __byte_perm(Fprev, 0, Sp);
    unsigned s_in = X & 3u;

    unsigned spikes = (s_in == 0) ? spk0 : ((s_in == 1) ? spk1 : spk2);

    // ---- Scatter spike floats into own sU range (no pre-sync needed) ----
    #pragma unroll
    for (int c = 0; c < 8; c++) {
        float4 s;
        s.x = ((spikes >> (4 * c + 0)) & 1u) ? 1.0f : 0.0f;
        s.y = ((spikes >> (4 * c + 1)) & 1u) ? 1.0f : 0.0f;
        s.z = ((spikes >> (4 * c + 2)) & 1u) ? 1.0f : 0.0f;
        s.w = ((spikes >> (4 * c + 3)) & 1u) ? 1.0f : 0.0f;
        *(float4*)(sU + tb + 4 * c) = s;
    }
    __syncthreads();

    // ---- Coalesced vector store (scalar fallback for the last block) ----
    const long long obase = (long long)blockIdx.x * TILE;
    if (obase + TILE <= (long long)N) {
        float4* gO4 = (float4*)(gOut + obase);
        for (int k4 = tid; k4 < TILE / 4; k4 += THREADS)       // 7-8 iters
            gO4[k4] = *(const float4*)(sU + padw4(k4) + 576);  // padw(512+e)
    } else {
        for (int k = tid; k < TILE; k += THREADS) {
            long long g = obase + k;
            if (g < (long long)N) gOut[g] = sU[padw(HALO + k)];
        }
    }
}

extern "C" void kernel_launch(void* const* d_in, const int* in_sizes, int n_in,
                              void* d_out, int out_size)
{
    const float* I   = (const float*)d_in[0];
    const float* u   = (const float*)d_in[1];
    const float* tau = (const float*)d_in[2];
    const float* thr = (const float*)d_in[3];
    float* out = (float*)d_out;
    const int N = in_sizes[0];

    const int blocks = (N + TILE - 1) / TILE;                  // 1093
    const size_t smem = (size_t)(2 * AWORDS + 24) * sizeof(float);

    cudaFuncSetAttribute(neuron_kernel,
                         cudaFuncAttributeMaxDynamicSharedMemorySize, (int)smem);

    neuron_kernel<<<blocks, THREADS, smem>>>(I, u, tau, thr, out, N);
}